// round 1
// baseline (speedup 1.0000x reference)
#include <cuda_runtime.h>

typedef unsigned long long ull;

#define THREADS 256
#define TILE    128
#define HDIM    128
#define FDIM    13
#define ODIM    64
#define NREF    10

#define INV_PI   0.31830988618379067f
#define INV_2PI  0.15915494309189535f

// ---------------- packed f32x2 helpers (Blackwell) ----------------
__device__ __forceinline__ ull pack2(float lo, float hi) {
    ull r; asm("mov.b64 %0, {%1, %2};" : "=l"(r) : "f"(lo), "f"(hi)); return r;
}
__device__ __forceinline__ void unpack2(ull v, float& lo, float& hi) {
    asm("mov.b64 {%0, %1}, %2;" : "=f"(lo), "=f"(hi) : "l"(v));
}
__device__ __forceinline__ ull ffma2(ull a, ull b, ull c) {
    ull d; asm("fma.rn.f32x2 %0, %1, %2, %3;" : "=l"(d) : "l"(a), "l"(b), "l"(c)); return d;
}

// ---------------- shared memory layout (all offsets 16B aligned) ----------------
struct __align__(16) SMem {
    float W1[FDIM * HDIM];                 // [k][j]
    float b1[HDIM]; float g1[HDIM]; float bt1[HDIM];
    float W2[HDIM * HDIM];                 // [k][j]
    float b2[HDIM]; float g2[HDIM]; float bt2[HDIM];
    float W3[HDIM * ODIM];                 // [k][j]
    float b3[ODIM];
    float rc[16]; float rs[16]; float rp[16];
    float feats[TILE * FDIM];              // [p][k]  (stride 13 -> conflict-free)
    float act[HDIM * TILE];                // [col][p]
    float sred[2 * TILE];
    float s2red[2 * TILE];
};

// LayerNorm (over 128 cols, split across 2 threads/point) + ReLU, write act[col][p].
// acc: 32 f32x2 pairs covering cols [jbase, jbase+64).
__device__ __forceinline__ void ln_relu_store(SMem* s, ull* acc, int jbase, int p, int tid,
                                              const float* g, const float* bt) {
    float sum = 0.0f, ssq = 0.0f;
    #pragma unroll
    for (int jj = 0; jj < 32; jj++) {
        float x0, x1; unpack2(acc[jj], x0, x1);
        sum += x0 + x1;
        ssq = fmaf(x0, x0, ssq);
        ssq = fmaf(x1, x1, ssq);
    }
    s->sred[tid] = sum;
    s->s2red[tid] = ssq;
    __syncthreads();
    float st = s->sred[p] + s->sred[TILE + p];
    float sq = s->s2red[p] + s->s2red[TILE + p];
    float mu = st * (1.0f / HDIM);
    float var = sq * (1.0f / HDIM) - mu * mu;
    float rstd = rsqrtf(var + 1e-5f);
    #pragma unroll
    for (int jj = 0; jj < 32; jj++) {
        int c = jbase + 2 * jj;
        float x0, x1; unpack2(acc[jj], x0, x1);
        float y0 = fmaxf(fmaf((x0 - mu) * rstd, g[c],     bt[c]),     0.0f);
        float y1 = fmaxf(fmaf((x1 - mu) * rstd, g[c + 1], bt[c + 1]), 0.0f);
        s->act[c * TILE + p]       = y0;
        s->act[(c + 1) * TILE + p] = y1;
    }
    __syncthreads();
}

__global__ __launch_bounds__(THREADS, 1)
void trunk_kernel(const float* __restrict__ coords,
                  const float* __restrict__ ref_theta, const float* __restrict__ ref_phi,
                  const float* __restrict__ W1, const float* __restrict__ b1,
                  const float* __restrict__ g1, const float* __restrict__ bt1,
                  const float* __restrict__ W2, const float* __restrict__ b2,
                  const float* __restrict__ g2, const float* __restrict__ bt2,
                  const float* __restrict__ W3, const float* __restrict__ b3,
                  float* __restrict__ out, int ntiles) {
    extern __shared__ float smem_raw[];
    SMem* s = reinterpret_cast<SMem*>(smem_raw);
    const int tid = threadIdx.x;

    // ---- one-time weight staging ----
    for (int i = tid; i < FDIM * HDIM; i += THREADS) s->W1[i] = W1[i];
    for (int i = tid; i < HDIM * HDIM; i += THREADS) s->W2[i] = W2[i];
    for (int i = tid; i < HDIM * ODIM; i += THREADS) s->W3[i] = W3[i];
    for (int i = tid; i < HDIM; i += THREADS) {
        s->b1[i] = b1[i]; s->g1[i] = g1[i]; s->bt1[i] = bt1[i];
        s->b2[i] = b2[i]; s->g2[i] = g2[i]; s->bt2[i] = bt2[i];
    }
    for (int i = tid; i < ODIM; i += THREADS) s->b3[i] = b3[i];
    if (tid < NREF) {
        float t = ref_theta[tid];
        s->rc[tid] = cosf(t);
        s->rs[tid] = sinf(t);
        s->rp[tid] = ref_phi[tid];
    }
    __syncthreads();

    const int p = tid & (TILE - 1);
    const int half = tid >> 7;           // 0 or 1

    for (int tile = blockIdx.x; tile < ntiles; tile += gridDim.x) {
        const int pg0 = tile * TILE;

        // ---- Phase F: geometric features (threads 0..127, one point each) ----
        if (tid < TILE) {
            int pg = pg0 + tid;
            float th = coords[2 * pg];
            float ph = coords[2 * pg + 1];
            float ct = cosf(th), stt = sinf(th);
            float* fr = &s->feats[tid * FDIM];
            #pragma unroll
            for (int r = 0; r < NREF; r++) {
                float cd = ct * s->rc[r] + stt * s->rs[r] * cosf(ph - s->rp[r]);
                cd = fminf(fmaxf(cd, -1.0f), 1.0f);
                fr[r] = acosf(cd) * INV_PI;
            }
            fr[10] = th * INV_PI;
            fr[11] = ph * INV_2PI;
            fr[12] = 1.0f;
        }
        __syncthreads();

        // ---- L1: feats[13] @ W1[13,128] + b1, 64 cols per thread ----
        {
            const int jbase = half * 64;
            ull f2[FDIM];
            #pragma unroll
            for (int k = 0; k < FDIM; k++) {
                float fv = s->feats[p * FDIM + k];
                f2[k] = pack2(fv, fv);
            }
            ull acc[32];
            const ulonglong2* bp = reinterpret_cast<const ulonglong2*>(s->b1 + jbase);
            #pragma unroll
            for (int jj = 0; jj < 16; jj++) { ulonglong2 v = bp[jj]; acc[2*jj] = v.x; acc[2*jj+1] = v.y; }
            #pragma unroll
            for (int k = 0; k < FDIM; k++) {
                const ulonglong2* wp = reinterpret_cast<const ulonglong2*>(s->W1 + k * HDIM + jbase);
                #pragma unroll
                for (int jj = 0; jj < 16; jj++) {
                    ulonglong2 w = wp[jj];
                    acc[2*jj]   = ffma2(f2[k], w.x, acc[2*jj]);
                    acc[2*jj+1] = ffma2(f2[k], w.y, acc[2*jj+1]);
                }
            }
            ln_relu_store(s, acc, jbase, p, tid, s->g1, s->bt1);
        }

        // ---- L2: act[128] @ W2[128,128] + b2 ----
        {
            const int jbase = half * 64;
            ull acc[32];
            const ulonglong2* bp = reinterpret_cast<const ulonglong2*>(s->b2 + jbase);
            #pragma unroll
            for (int jj = 0; jj < 16; jj++) { ulonglong2 v = bp[jj]; acc[2*jj] = v.x; acc[2*jj+1] = v.y; }
            #pragma unroll 4
            for (int k = 0; k < HDIM; k++) {
                float a = s->act[k * TILE + p];
                ull a2 = pack2(a, a);
                const ulonglong2* wp = reinterpret_cast<const ulonglong2*>(s->W2 + k * HDIM + jbase);
                #pragma unroll
                for (int jj = 0; jj < 16; jj++) {
                    ulonglong2 w = wp[jj];
                    acc[2*jj]   = ffma2(a2, w.x, acc[2*jj]);
                    acc[2*jj+1] = ffma2(a2, w.y, acc[2*jj+1]);
                }
            }
            ln_relu_store(s, acc, jbase, p, tid, s->g2, s->bt2);
        }

        // ---- L3: act[128] @ W3[128,64] + b3, 32 cols per thread, direct STG.128 ----
        {
            const int jbase = half * 32;
            ull acc[16];
            const ulonglong2* bp = reinterpret_cast<const ulonglong2*>(s->b3 + jbase);
            #pragma unroll
            for (int jj = 0; jj < 8; jj++) { ulonglong2 v = bp[jj]; acc[2*jj] = v.x; acc[2*jj+1] = v.y; }
            #pragma unroll 4
            for (int k = 0; k < HDIM; k++) {
                float a = s->act[k * TILE + p];
                ull a2 = pack2(a, a);
                const ulonglong2* wp = reinterpret_cast<const ulonglong2*>(s->W3 + k * ODIM + jbase);
                #pragma unroll
                for (int jj = 0; jj < 8; jj++) {
                    ulonglong2 w = wp[jj];
                    acc[2*jj]   = ffma2(a2, w.x, acc[2*jj]);
                    acc[2*jj+1] = ffma2(a2, w.y, acc[2*jj+1]);
                }
            }
            float* op = out + (size_t)(pg0 + p) * ODIM + jbase;
            #pragma unroll
            for (int jj = 0; jj < 4; jj++) {
                float x0, x1, x2, x3;
                unpack2(acc[4*jj],     x0, x1);
                unpack2(acc[4*jj + 1], x2, x3);
                float4 v0 = make_float4(x0, x1, x2, x3);
                unpack2(acc[4*jj + 2], x0, x1);
                unpack2(acc[4*jj + 3], x2, x3);
                float4 v1 = make_float4(x0, x1, x2, x3);
                reinterpret_cast<float4*>(op)[2*jj]     = v0;
                reinterpret_cast<float4*>(op)[2*jj + 1] = v1;
            }
        }
        // no trailing sync needed: next iteration's first write (feats) only
        // lands after S1, and act writes only after next LN1's internal sync.
        __syncthreads();
    }
}

extern "C" void kernel_launch(void* const* d_in, const int* in_sizes, int n_in,
                              void* d_out, int out_size) {
    const float* coords    = (const float*)d_in[0];
    const float* ref_theta = (const float*)d_in[1];
    const float* ref_phi   = (const float*)d_in[2];
    const float* W1  = (const float*)d_in[3];
    const float* b1  = (const float*)d_in[4];
    const float* g1  = (const float*)d_in[5];
    const float* bt1 = (const float*)d_in[6];
    const float* W2  = (const float*)d_in[7];
    const float* b2  = (const float*)d_in[8];
    const float* g2  = (const float*)d_in[9];
    const float* bt2 = (const float*)d_in[10];
    const float* W3  = (const float*)d_in[11];
    const float* b3  = (const float*)d_in[12];
    float* out = (float*)d_out;

    int npoints = in_sizes[0] / 2;       // coords is [B, N, 2]
    int ntiles = npoints / TILE;

    cudaFuncSetAttribute(trunk_kernel, cudaFuncAttributeMaxDynamicSharedMemorySize,
                         (int)sizeof(SMem));
    trunk_kernel<<<148, THREADS, sizeof(SMem)>>>(
        coords, ref_theta, ref_phi,
        W1, b1, g1, bt1, W2, b2, g2, bt2, W3, b3,
        out, ntiles);
}

// round 5
// speedup vs baseline: 2.4728x; 2.4728x over previous
#include <cuda_runtime.h>
#include <cuda_bf16.h>
#include <cstdint>

#define THREADS 256
#define TILE    128
#define HDIM    128
#define FDIM    13
#define ODIM    64
#define NREF    10

#define INV_PI   0.31830988618379067f
#define INV_2PI  0.15915494309189535f

// ---------------- shared memory byte offsets ----------------
#define SM_RC     0
#define SM_RS     64
#define SM_RP     128
#define SM_B1     192
#define SM_G1     704
#define SM_BT1    1216
#define SM_B2     1728
#define SM_G2     2240
#define SM_BT2    2752
#define SM_B3     3264
#define SM_SRED   3520
#define SM_S2RED  4544
#define SM_X      5632          /* 69632-byte multi-role region */
#define SM_ACT_L  (SM_X + 34816)
#define SM_F1H    (SM_X + 69632)   /* 75264 */
#define SM_F1L    (SM_F1H + 4096)
#define SM_F2H    (SM_F1L + 4096)
#define SM_F2L    (SM_F2H + 32768)
#define SM_F3H    (SM_F2L + 32768)
#define SM_F3L    (SM_F3H + 16384)
#define SM_TOTAL  (SM_F3L + 16384) /* 181760 bytes */

// act layout: bf16 [128 rows][136 cols] (stride 68 32-bit words)
// D   layout: fp32 [128 rows][132 cols]

// ---------------- helpers ----------------
__device__ __forceinline__ void bsplit(float v, uint16_t& h, uint16_t& l) {
    __nv_bfloat16 hb = __float2bfloat16_rn(v);
    float r = v - __bfloat162float(hb);
    __nv_bfloat16 lb = __float2bfloat16_rn(r);
    h = __bfloat16_as_ushort(hb);
    l = __bfloat16_as_ushort(lb);
}
__device__ __forceinline__ uint32_t packu(uint16_t lo, uint16_t hi) {
    return ((uint32_t)hi << 16) | (uint32_t)lo;
}

// mma.sync m16n8k16 bf16: D += A*B  (fp32 accum)
__device__ __forceinline__ void mma16816(float* d, const uint32_t* a, uint32_t b0, uint32_t b1) {
    asm volatile(
        "mma.sync.aligned.m16n8k16.row.col.f32.bf16.bf16.f32 "
        "{%0,%1,%2,%3}, {%4,%5,%6,%7}, {%8,%9}, {%0,%1,%2,%3};"
        : "+f"(d[0]), "+f"(d[1]), "+f"(d[2]), "+f"(d[3])
        : "r"(a[0]), "r"(a[1]), "r"(a[2]), "r"(a[3]), "r"(b0), "r"(b1));
}

// One GEMM pass: acc[mt][nt][4] += act(X) @ Wfrag ; warp owns 32 rows x (NTW*8) cols
template<int KS, int NTW, int NT_TOTAL>
__device__ __forceinline__ void mma_layer(char* smem, int fh_off, int fl_off,
                                          int wm, int wn, int gid, int tg, int lane,
                                          float* acc) {
    const uint32_t* AH = (const uint32_t*)(smem + SM_X);
    const uint32_t* AL = (const uint32_t*)(smem + SM_ACT_L);
    const uint32_t* FH = (const uint32_t*)(smem + fh_off);
    const uint32_t* FL = (const uint32_t*)(smem + fl_off);
    #pragma unroll
    for (int ks = 0; ks < KS; ks++) {
        uint32_t aH[2][4], aL[2][4];
        const int kc = ks * 8 + tg;
        #pragma unroll
        for (int mt = 0; mt < 2; mt++) {
            int r0 = wm * 32 + mt * 16 + gid;
            aH[mt][0] = AH[r0 * 68 + kc];
            aH[mt][1] = AH[(r0 + 8) * 68 + kc];
            aH[mt][2] = AH[r0 * 68 + kc + 4];
            aH[mt][3] = AH[(r0 + 8) * 68 + kc + 4];
            aL[mt][0] = AL[r0 * 68 + kc];
            aL[mt][1] = AL[(r0 + 8) * 68 + kc];
            aL[mt][2] = AL[r0 * 68 + kc + 4];
            aL[mt][3] = AL[(r0 + 8) * 68 + kc + 4];
        }
        #pragma unroll
        for (int nt = 0; nt < NTW; nt++) {
            int ng = wn * NTW + nt;
            const uint32_t* fh = FH + (size_t)((ks * NT_TOTAL + ng) * 2) * 32 + lane;
            const uint32_t* fl = FL + (size_t)((ks * NT_TOTAL + ng) * 2) * 32 + lane;
            uint32_t bh0 = fh[0], bh1 = fh[32];
            uint32_t bl0 = fl[0], bl1 = fl[32];
            #pragma unroll
            for (int mt = 0; mt < 2; mt++) {
                float* a = acc + (size_t)(mt * NTW + nt) * 4;
                mma16816(a, aH[mt], bh0, bh1);
                mma16816(a, aL[mt], bh0, bh1);
                mma16816(a, aH[mt], bl0, bl1);
            }
        }
    }
}

// Scatter accumulator fragments into D (fp32, stride 132)
template<int NTW>
__device__ __forceinline__ void store_D(char* smem, int wm, int wn, int gid, int tg,
                                        const float* acc) {
    float* D = (float*)(smem + SM_X);
    #pragma unroll
    for (int mt = 0; mt < 2; mt++) {
        int r0 = wm * 32 + mt * 16 + gid;
        #pragma unroll
        for (int nt = 0; nt < NTW; nt++) {
            int col = (wn * NTW + nt) * 8 + tg * 2;
            const float* a = acc + (size_t)(mt * NTW + nt) * 4;
            *(float2*)(D + r0 * 132 + col)       = make_float2(a[0], a[1]);
            *(float2*)(D + (r0 + 8) * 132 + col) = make_float2(a[2], a[3]);
        }
    }
}

// LayerNorm epilogue: read D row (thread owns row p, 64-col half), add bias,
// normalize, gamma/beta, ReLU, bf16-split, store act hi/lo back into X.
__device__ __forceinline__ void ln_epilogue(char* smem, int p, int half, int tid,
                                            const float* bias, const float* g,
                                            const float* bt) {
    float* D = (float*)(smem + SM_X);
    float* s_sred = (float*)(smem + SM_SRED);
    float* s_s2red = (float*)(smem + SM_S2RED);
    float x[64];
    const float4* row = (const float4*)(D + p * 132 + half * 64);
    float sum = 0.0f, ssq = 0.0f;
    #pragma unroll
    for (int q = 0; q < 16; q++) {
        float4 v = row[q];
        int c = half * 64 + 4 * q;
        x[4*q]   = v.x + bias[c];
        x[4*q+1] = v.y + bias[c+1];
        x[4*q+2] = v.z + bias[c+2];
        x[4*q+3] = v.w + bias[c+3];
        sum += x[4*q] + x[4*q+1] + x[4*q+2] + x[4*q+3];
        ssq = fmaf(x[4*q],   x[4*q],   ssq);
        ssq = fmaf(x[4*q+1], x[4*q+1], ssq);
        ssq = fmaf(x[4*q+2], x[4*q+2], ssq);
        ssq = fmaf(x[4*q+3], x[4*q+3], ssq);
    }
    s_sred[tid] = sum; s_s2red[tid] = ssq;
    __syncthreads();   // also guarantees all D reads done before act overwrite
    float st = s_sred[p] + s_sred[TILE + p];
    float sq = s_s2red[p] + s_s2red[TILE + p];
    float mu = st * (1.0f / HDIM);
    float var = sq * (1.0f / HDIM) - mu * mu;
    float rstd = rsqrtf(var + 1e-5f);
    uint32_t wh[32], wl[32];
    #pragma unroll
    for (int j = 0; j < 32; j++) {
        int c = half * 64 + 2 * j;
        float y0 = fmaxf(fmaf((x[2*j]   - mu) * rstd, g[c],   bt[c]),   0.0f);
        float y1 = fmaxf(fmaf((x[2*j+1] - mu) * rstd, g[c+1], bt[c+1]), 0.0f);
        uint16_t h0, l0, h1, l1;
        bsplit(y0, h0, l0);
        bsplit(y1, h1, l1);
        wh[j] = packu(h0, h1);
        wl[j] = packu(l0, l1);
    }
    __syncthreads();
    uint32_t* AH = (uint32_t*)(smem + SM_X);
    uint32_t* ALo = (uint32_t*)(smem + SM_ACT_L);
    uint4* dh = (uint4*)(AH + p * 68 + half * 32);
    uint4* dl = (uint4*)(ALo + p * 68 + half * 32);
    #pragma unroll
    for (int q = 0; q < 8; q++) {
        dh[q] = make_uint4(wh[4*q], wh[4*q+1], wh[4*q+2], wh[4*q+3]);
        dl[q] = make_uint4(wl[4*q], wl[4*q+1], wl[4*q+2], wl[4*q+3]);
    }
    __syncthreads();
}

__global__ __launch_bounds__(THREADS, 1)
void trunk_kernel(const float* __restrict__ coords,
                  const float* __restrict__ ref_theta, const float* __restrict__ ref_phi,
                  const float* __restrict__ W1, const float* __restrict__ b1,
                  const float* __restrict__ g1, const float* __restrict__ bt1,
                  const float* __restrict__ W2, const float* __restrict__ b2,
                  const float* __restrict__ g2, const float* __restrict__ bt2,
                  const float* __restrict__ W3, const float* __restrict__ b3,
                  float* __restrict__ out, int ntiles) {
    extern __shared__ char smem[];
    const int tid = threadIdx.x;
    const int lane = tid & 31;
    const int wid = tid >> 5;
    const int gid = lane >> 2;
    const int tg = lane & 3;
    const int wm = wid & 3;
    const int wn = wid >> 2;

    float* s_b1 = (float*)(smem + SM_B1);
    float* s_g1 = (float*)(smem + SM_G1);
    float* s_bt1 = (float*)(smem + SM_BT1);
    float* s_b2 = (float*)(smem + SM_B2);
    float* s_g2 = (float*)(smem + SM_G2);
    float* s_bt2 = (float*)(smem + SM_BT2);
    float* s_b3 = (float*)(smem + SM_B3);
    float* s_rc = (float*)(smem + SM_RC);
    float* s_rs = (float*)(smem + SM_RS);
    float* s_rp = (float*)(smem + SM_RP);

    // ---- one-time staging: biases / LN params / refs ----
    for (int i = tid; i < HDIM; i += THREADS) {
        s_b1[i] = b1[i]; s_g1[i] = g1[i]; s_bt1[i] = bt1[i];
        s_b2[i] = b2[i]; s_g2[i] = g2[i]; s_bt2[i] = bt2[i];
    }
    for (int i = tid; i < ODIM; i += THREADS) s_b3[i] = b3[i];
    if (tid < NREF) {
        float t = ref_theta[tid];
        s_rc[tid] = cosf(t); s_rs[tid] = sinf(t); s_rp[tid] = ref_phi[tid];
    }

    // ---- one-time fragment-ordered weight conversion ----
    // layout: word index = ((ks*NT + ntile)*2 + reg)*32 + lane
    {
        uint32_t* F1H = (uint32_t*)(smem + SM_F1H);
        uint32_t* F1L = (uint32_t*)(smem + SM_F1L);
        for (int idx = tid; idx < 1024; idx += THREADS) {   // 1 ks, 16 nt
            int ln = idx & 31, rest = idx >> 5;
            int reg = rest & 1, nt = rest >> 1;             // nt 0..15
            int n = nt * 8 + (ln >> 2);
            int k = reg * 8 + (ln & 3) * 2;
            float w0 = (k < FDIM)     ? W1[k * HDIM + n]       : 0.0f;
            float w1 = (k + 1 < FDIM) ? W1[(k + 1) * HDIM + n] : 0.0f;
            uint16_t h0, l0, h1, l1;
            bsplit(w0, h0, l0); bsplit(w1, h1, l1);
            F1H[idx] = packu(h0, h1);
            F1L[idx] = packu(l0, l1);
        }
        uint32_t* F2H = (uint32_t*)(smem + SM_F2H);
        uint32_t* F2L = (uint32_t*)(smem + SM_F2L);
        for (int idx = tid; idx < 8192; idx += THREADS) {   // 8 ks, 16 nt
            int ln = idx & 31, rest = idx >> 5;
            int reg = rest & 1, ntk = rest >> 1;
            int nt = ntk & 15, ks = ntk >> 4;
            int n = nt * 8 + (ln >> 2);
            int k = ks * 16 + reg * 8 + (ln & 3) * 2;
            float w0 = W2[k * HDIM + n];
            float w1 = W2[(k + 1) * HDIM + n];
            uint16_t h0, l0, h1, l1;
            bsplit(w0, h0, l0); bsplit(w1, h1, l1);
            F2H[idx] = packu(h0, h1);
            F2L[idx] = packu(l0, l1);
        }
        uint32_t* F3H = (uint32_t*)(smem + SM_F3H);
        uint32_t* F3L = (uint32_t*)(smem + SM_F3L);
        for (int idx = tid; idx < 4096; idx += THREADS) {   // 8 ks, 8 nt
            int ln = idx & 31, rest = idx >> 5;
            int reg = rest & 1, ntk = rest >> 1;
            int nt = ntk & 7, ks = ntk >> 3;
            int n = nt * 8 + (ln >> 2);
            int k = ks * 16 + reg * 8 + (ln & 3) * 2;
            float w0 = W3[k * ODIM + n];
            float w1 = W3[(k + 1) * ODIM + n];
            uint16_t h0, l0, h1, l1;
            bsplit(w0, h0, l0); bsplit(w1, h1, l1);
            F3H[idx] = packu(h0, h1);
            F3L[idx] = packu(l0, l1);
        }
    }
    __syncthreads();

    const int p = tid & (TILE - 1);
    const int half = tid >> 7;

    for (int tile = blockIdx.x; tile < ntiles; tile += gridDim.x) {
        const int pg0 = tile * TILE;

        // ---- feats -> act0 (bf16 hi/lo, rows [p][cols 0..15]) ----
        if (tid < TILE) {
            int pg = pg0 + tid;
            float th = coords[2 * pg];
            float phc = coords[2 * pg + 1];
            float ct = cosf(th), stt = sinf(th);
            float fr[16];
            #pragma unroll
            for (int r = 0; r < NREF; r++) {
                float cd = ct * s_rc[r] + stt * s_rs[r] * cosf(phc - s_rp[r]);
                cd = fminf(fmaxf(cd, -1.0f), 1.0f);
                fr[r] = acosf(cd) * INV_PI;
            }
            fr[10] = th * INV_PI;
            fr[11] = phc * INV_2PI;
            fr[12] = 1.0f;
            fr[13] = 0.0f; fr[14] = 0.0f; fr[15] = 0.0f;
            uint32_t wh[8], wl[8];
            #pragma unroll
            for (int j = 0; j < 8; j++) {
                uint16_t h0, l0, h1, l1;
                bsplit(fr[2*j],   h0, l0);
                bsplit(fr[2*j+1], h1, l1);
                wh[j] = packu(h0, h1);
                wl[j] = packu(l0, l1);
            }
            uint4* dh = (uint4*)((uint32_t*)(smem + SM_X) + tid * 68);
            uint4* dl = (uint4*)((uint32_t*)(smem + SM_ACT_L) + tid * 68);
            dh[0] = make_uint4(wh[0], wh[1], wh[2], wh[3]);
            dh[1] = make_uint4(wh[4], wh[5], wh[6], wh[7]);
            dl[0] = make_uint4(wl[0], wl[1], wl[2], wl[3]);
            dl[1] = make_uint4(wl[4], wl[5], wl[6], wl[7]);
        }
        __syncthreads();

        // ---- L1: act0 @ W1  (K=16, N=128) ----
        {
            float acc[2 * 8 * 4];
            #pragma unroll
            for (int i = 0; i < 64; i++) acc[i] = 0.0f;
            mma_layer<1, 8, 16>(smem, SM_F1H, SM_F1L, wm, wn, gid, tg, lane, acc);
            __syncthreads();
            store_D<8>(smem, wm, wn, gid, tg, acc);
            __syncthreads();
            ln_epilogue(smem, p, half, tid, s_b1, s_g1, s_bt1);
        }

        // ---- L2: act1 @ W2  (K=128, N=128) ----
        {
            float acc[2 * 8 * 4];
            #pragma unroll
            for (int i = 0; i < 64; i++) acc[i] = 0.0f;
            mma_layer<8, 8, 16>(smem, SM_F2H, SM_F2L, wm, wn, gid, tg, lane, acc);
            __syncthreads();
            store_D<8>(smem, wm, wn, gid, tg, acc);
            __syncthreads();
            ln_epilogue(smem, p, half, tid, s_b2, s_g2, s_bt2);
        }

        // ---- L3: act2 @ W3  (K=128, N=64) -> GMEM directly ----
        {
            float acc[2 * 4 * 4];
            #pragma unroll
            for (int i = 0; i < 32; i++) acc[i] = 0.0f;
            mma_layer<8, 4, 8>(smem, SM_F3H, SM_F3L, wm, wn, gid, tg, lane, acc);
            #pragma unroll
            for (int mt = 0; mt < 2; mt++) {
                int r0 = wm * 32 + mt * 16 + gid;
                #pragma unroll
                for (int nt = 0; nt < 4; nt++) {
                    int col = (wn * 4 + nt) * 8 + tg * 2;
                    const float* a = acc + (size_t)(mt * 4 + nt) * 4;
                    float2 v0 = make_float2(a[0] + s_b3[col], a[1] + s_b3[col + 1]);
                    float2 v1 = make_float2(a[2] + s_b3[col], a[3] + s_b3[col + 1]);
                    *(float2*)(out + (size_t)(pg0 + r0) * ODIM + col)     = v0;
                    *(float2*)(out + (size_t)(pg0 + r0 + 8) * ODIM + col) = v1;
                }
            }
        }
        __syncthreads();   // X free for next tile
    }
}

extern "C" void kernel_launch(void* const* d_in, const int* in_sizes, int n_in,
                              void* d_out, int out_size) {
    const float* coords    = (const float*)d_in[0];
    const float* ref_theta = (const float*)d_in[1];
    const float* ref_phi   = (const float*)d_in[2];
    const float* W1  = (const float*)d_in[3];
    const float* b1  = (const float*)d_in[4];
    const float* g1  = (const float*)d_in[5];
    const float* bt1 = (const float*)d_in[6];
    const float* W2  = (const float*)d_in[7];
    const float* b2  = (const float*)d_in[8];
    const float* g2  = (const float*)d_in[9];
    const float* bt2 = (const float*)d_in[10];
    const float* W3  = (const float*)d_in[11];
    const float* b3  = (const float*)d_in[12];
    float* out = (float*)d_out;

    int npoints = in_sizes[0] / 2;
    int ntiles = npoints / TILE;

    cudaFuncSetAttribute(trunk_kernel, cudaFuncAttributeMaxDynamicSharedMemorySize, SM_TOTAL);
    trunk_kernel<<<148, THREADS, SM_TOTAL>>>(
        coords, ref_theta, ref_phi,
        W1, b1, g1, bt1, W2, b2, g2, bt2, W3, b3,
        out, ntiles);
}

// round 6
// speedup vs baseline: 2.6324x; 1.0646x over previous
#include <cuda_runtime.h>
#include <cuda_bf16.h>
#include <cstdint>

#define THREADS 256
#define TILE    128
#define HDIM    128
#define FDIM    13
#define ODIM    64
#define NREF    10

#define INV_PI   0.31830988618379067f
#define INV_2PI  0.15915494309189535f

// ---------------- shared memory byte offsets ----------------
#define SM_RC     0
#define SM_RS     64
#define SM_RP     128
#define SM_B1     192
#define SM_G1     704
#define SM_BT1    1216
#define SM_B2     1728
#define SM_G2     2240
#define SM_BT2    2752
#define SM_B3     3264
#define SM_SRED   3520          /* 256 floats: [wn][row] */
#define SM_S2RED  4544          /* 256 floats */
#define SM_ACT    5632          /* uint2[128][68] = 69632 B (hiPair, loPair) */
#define SM_F1H    (SM_ACT + 69632)   /* 75264 */
#define SM_F1L    (SM_F1H + 4096)
#define SM_F2H    (SM_F1L + 4096)
#define SM_F2L    (SM_F2H + 32768)
#define SM_F3H    (SM_F2L + 32768)
#define SM_F3L    (SM_F3H + 16384)
#define SM_TOTAL  (SM_F3L + 16384) /* 181760 bytes */

// ---------------- helpers ----------------
__device__ __forceinline__ void bsplit(float v, uint16_t& h, uint16_t& l) {
    __nv_bfloat16 hb = __float2bfloat16_rn(v);
    float r = v - __bfloat162float(hb);
    __nv_bfloat16 lb = __float2bfloat16_rn(r);
    h = __bfloat16_as_ushort(hb);
    l = __bfloat16_as_ushort(lb);
}
__device__ __forceinline__ uint32_t packu(uint16_t lo, uint16_t hi) {
    return ((uint32_t)hi << 16) | (uint32_t)lo;
}
// fast split of a value pair: hi = truncate-to-bf16 (exact residual), lo = rn(residual)
__device__ __forceinline__ uint2 pack_split(float y0, float y1) {
    uint32_t b0 = __float_as_uint(y0), b1 = __float_as_uint(y1);
    float l0 = y0 - __uint_as_float(b0 & 0xFFFF0000u);
    float l1 = y1 - __uint_as_float(b1 & 0xFFFF0000u);
    uint32_t hp = __byte_perm(b0, b1, 0x7632);   // {hi16(b1), hi16(b0)}
    uint32_t lp;
    asm("cvt.rn.bf16x2.f32 %0, %1, %2;" : "=r"(lp) : "f"(l1), "f"(l0));
    return make_uint2(hp, lp);
}

// mma.sync m16n8k16 bf16: D += A*B  (fp32 accum)
__device__ __forceinline__ void mma16816(float* d, const uint32_t* a, uint32_t b0, uint32_t b1) {
    asm volatile(
        "mma.sync.aligned.m16n8k16.row.col.f32.bf16.bf16.f32 "
        "{%0,%1,%2,%3}, {%4,%5,%6,%7}, {%8,%9}, {%0,%1,%2,%3};"
        : "+f"(d[0]), "+f"(d[1]), "+f"(d[2]), "+f"(d[3])
        : "r"(a[0]), "r"(a[1]), "r"(a[2]), "r"(a[3]), "r"(b0), "r"(b1));
}

// One GEMM pass: acc[mt][nt][4] += act @ Wfrag ; warp owns 32 rows x (NTW*8) cols
template<int KS, int NTW, int NT_TOTAL>
__device__ __forceinline__ void mma_layer(char* smem, int fh_off, int fl_off,
                                          int wm, int wn, int gid, int tg, int lane,
                                          float* acc) {
    const uint2* A = (const uint2*)(smem + SM_ACT);
    const uint32_t* FH = (const uint32_t*)(smem + fh_off);
    const uint32_t* FL = (const uint32_t*)(smem + fl_off);
    #pragma unroll
    for (int ks = 0; ks < KS; ks++) {
        const int kc = ks * 8 + tg;
        uint32_t aH[2][4], aL[2][4];
        #pragma unroll
        for (int mt = 0; mt < 2; mt++) {
            int r0 = wm * 32 + mt * 16 + gid;
            uint2 v0 = A[r0 * 68 + kc];
            uint2 v1 = A[(r0 + 8) * 68 + kc];
            uint2 v2 = A[r0 * 68 + kc + 4];
            uint2 v3 = A[(r0 + 8) * 68 + kc + 4];
            aH[mt][0] = v0.x; aH[mt][1] = v1.x; aH[mt][2] = v2.x; aH[mt][3] = v3.x;
            aL[mt][0] = v0.y; aL[mt][1] = v1.y; aL[mt][2] = v2.y; aL[mt][3] = v3.y;
        }
        #pragma unroll
        for (int nt = 0; nt < NTW; nt++) {
            int ng = wn * NTW + nt;
            const uint32_t* fh = FH + (size_t)((ks * NT_TOTAL + ng) * 2) * 32 + lane;
            const uint32_t* fl = FL + (size_t)((ks * NT_TOTAL + ng) * 2) * 32 + lane;
            uint32_t bh0 = fh[0], bh1 = fh[32];
            uint32_t bl0 = fl[0], bl1 = fl[32];
            #pragma unroll
            for (int mt = 0; mt < 2; mt++) {
                float* a = acc + (size_t)(mt * NTW + nt) * 4;
                mma16816(a, aH[mt], bh0, bh1);
                mma16816(a, aL[mt], bh0, bh1);
                mma16816(a, aH[mt], bl0, bl1);
            }
        }
    }
}

// Fragment-resident LayerNorm + ReLU + split + act store (NTW=8 layers).
// acc rows: r(mt,h) = wm*32 + mt*16 + h*8 + gid ; cols: c = (wn*8+nt)*8 + 2tg + {0,1}
__device__ __forceinline__ void ln_frag_epilogue(char* smem, float* acc,
                                                 int wm, int wn, int gid, int tg,
                                                 const float* bias, const float* g,
                                                 const float* bt) {
    float* SS = (float*)(smem + SM_SRED);
    float* QQ = (float*)(smem + SM_S2RED);
    float s[2][2], q[2][2];
    #pragma unroll
    for (int mt = 0; mt < 2; mt++) { s[mt][0]=s[mt][1]=q[mt][0]=q[mt][1]=0.0f; }
    #pragma unroll
    for (int mt = 0; mt < 2; mt++) {
        #pragma unroll
        for (int nt = 0; nt < 8; nt++) {
            float* a = acc + (size_t)(mt * 8 + nt) * 4;
            int c0 = (wn * 8 + nt) * 8 + 2 * tg;
            float b0v = bias[c0], b1v = bias[c0 + 1];
            a[0] += b0v; a[1] += b1v; a[2] += b0v; a[3] += b1v;
            s[mt][0] += a[0] + a[1];
            q[mt][0] = fmaf(a[0], a[0], q[mt][0]);
            q[mt][0] = fmaf(a[1], a[1], q[mt][0]);
            s[mt][1] += a[2] + a[3];
            q[mt][1] = fmaf(a[2], a[2], q[mt][1]);
            q[mt][1] = fmaf(a[3], a[3], q[mt][1]);
        }
    }
    // reduce over the 4 tg lanes (lanes gid*4 + tg)
    #pragma unroll
    for (int mt = 0; mt < 2; mt++) {
        #pragma unroll
        for (int h = 0; h < 2; h++) {
            s[mt][h] += __shfl_xor_sync(0xffffffffu, s[mt][h], 1);
            s[mt][h] += __shfl_xor_sync(0xffffffffu, s[mt][h], 2);
            q[mt][h] += __shfl_xor_sync(0xffffffffu, q[mt][h], 1);
            q[mt][h] += __shfl_xor_sync(0xffffffffu, q[mt][h], 2);
        }
    }
    if (tg == 0) {
        #pragma unroll
        for (int mt = 0; mt < 2; mt++) {
            #pragma unroll
            for (int h = 0; h < 2; h++) {
                int row = wm * 32 + mt * 16 + h * 8 + gid;
                SS[wn * 128 + row] = s[mt][h];
                QQ[wn * 128 + row] = q[mt][h];
            }
        }
    }
    __syncthreads();   // also guarantees all MMA act-reads complete
    float mu[2][2], rs[2][2];
    #pragma unroll
    for (int mt = 0; mt < 2; mt++) {
        #pragma unroll
        for (int h = 0; h < 2; h++) {
            int row = wm * 32 + mt * 16 + h * 8 + gid;
            float st = SS[row] + SS[128 + row];
            float sq = QQ[row] + QQ[128 + row];
            float m = st * (1.0f / HDIM);
            float var = sq * (1.0f / HDIM) - m * m;
            mu[mt][h] = m;
            rs[mt][h] = rsqrtf(var + 1e-5f);
        }
    }
    uint2* ACT = (uint2*)(smem + SM_ACT);
    #pragma unroll
    for (int mt = 0; mt < 2; mt++) {
        int r0 = wm * 32 + mt * 16 + gid;
        #pragma unroll
        for (int nt = 0; nt < 8; nt++) {
            float* a = acc + (size_t)(mt * 8 + nt) * 4;
            int c0 = (wn * 8 + nt) * 8 + 2 * tg;
            float g0 = g[c0], g1 = g[c0 + 1], t0 = bt[c0], t1 = bt[c0 + 1];
            float y00 = fmaxf(fmaf((a[0] - mu[mt][0]) * rs[mt][0], g0, t0), 0.0f);
            float y01 = fmaxf(fmaf((a[1] - mu[mt][0]) * rs[mt][0], g1, t1), 0.0f);
            float y10 = fmaxf(fmaf((a[2] - mu[mt][1]) * rs[mt][1], g0, t0), 0.0f);
            float y11 = fmaxf(fmaf((a[3] - mu[mt][1]) * rs[mt][1], g1, t1), 0.0f);
            int w = (wn * 8 + nt) * 4 + tg;
            ACT[r0 * 68 + w]       = pack_split(y00, y01);
            ACT[(r0 + 8) * 68 + w] = pack_split(y10, y11);
        }
    }
    __syncthreads();
}

__global__ __launch_bounds__(THREADS, 1)
void trunk_kernel(const float* __restrict__ coords,
                  const float* __restrict__ ref_theta, const float* __restrict__ ref_phi,
                  const float* __restrict__ W1, const float* __restrict__ b1,
                  const float* __restrict__ g1, const float* __restrict__ bt1,
                  const float* __restrict__ W2, const float* __restrict__ b2,
                  const float* __restrict__ g2, const float* __restrict__ bt2,
                  const float* __restrict__ W3, const float* __restrict__ b3,
                  float* __restrict__ out, int ntiles) {
    extern __shared__ char smem[];
    const int tid = threadIdx.x;
    const int lane = tid & 31;
    const int wid = tid >> 5;
    const int gid = lane >> 2;
    const int tg = lane & 3;
    const int wm = wid & 3;
    const int wn = wid >> 2;

    float* s_b1 = (float*)(smem + SM_B1);
    float* s_g1 = (float*)(smem + SM_G1);
    float* s_bt1 = (float*)(smem + SM_BT1);
    float* s_b2 = (float*)(smem + SM_B2);
    float* s_g2 = (float*)(smem + SM_G2);
    float* s_bt2 = (float*)(smem + SM_BT2);
    float* s_b3 = (float*)(smem + SM_B3);
    float* s_rc = (float*)(smem + SM_RC);
    float* s_rs = (float*)(smem + SM_RS);
    float* s_rp = (float*)(smem + SM_RP);

    // ---- one-time staging: biases / LN params / refs ----
    for (int i = tid; i < HDIM; i += THREADS) {
        s_b1[i] = b1[i]; s_g1[i] = g1[i]; s_bt1[i] = bt1[i];
        s_b2[i] = b2[i]; s_g2[i] = g2[i]; s_bt2[i] = bt2[i];
    }
    for (int i = tid; i < ODIM; i += THREADS) s_b3[i] = b3[i];
    if (tid < NREF) {
        float t = ref_theta[tid];
        s_rc[tid] = cosf(t); s_rs[tid] = sinf(t); s_rp[tid] = ref_phi[tid];
    }

    // ---- one-time fragment-ordered weight conversion ----
    // layout: word index = ((ks*NT + ntile)*2 + reg)*32 + lane
    {
        uint32_t* F1H = (uint32_t*)(smem + SM_F1H);
        uint32_t* F1L = (uint32_t*)(smem + SM_F1L);
        for (int idx = tid; idx < 1024; idx += THREADS) {   // 1 ks, 16 nt
            int ln = idx & 31, rest = idx >> 5;
            int reg = rest & 1, nt = rest >> 1;
            int n = nt * 8 + (ln >> 2);
            int k = reg * 8 + (ln & 3) * 2;
            float w0 = (k < FDIM)     ? W1[k * HDIM + n]       : 0.0f;
            float w1 = (k + 1 < FDIM) ? W1[(k + 1) * HDIM + n] : 0.0f;
            uint16_t h0, l0, h1, l1;
            bsplit(w0, h0, l0); bsplit(w1, h1, l1);
            F1H[idx] = packu(h0, h1);
            F1L[idx] = packu(l0, l1);
        }
        uint32_t* F2H = (uint32_t*)(smem + SM_F2H);
        uint32_t* F2L = (uint32_t*)(smem + SM_F2L);
        for (int idx = tid; idx < 8192; idx += THREADS) {   // 8 ks, 16 nt
            int ln = idx & 31, rest = idx >> 5;
            int reg = rest & 1, ntk = rest >> 1;
            int nt = ntk & 15, ks = ntk >> 4;
            int n = nt * 8 + (ln >> 2);
            int k = ks * 16 + reg * 8 + (ln & 3) * 2;
            float w0 = W2[k * HDIM + n];
            float w1 = W2[(k + 1) * HDIM + n];
            uint16_t h0, l0, h1, l1;
            bsplit(w0, h0, l0); bsplit(w1, h1, l1);
            F2H[idx] = packu(h0, h1);
            F2L[idx] = packu(l0, l1);
        }
        uint32_t* F3H = (uint32_t*)(smem + SM_F3H);
        uint32_t* F3L = (uint32_t*)(smem + SM_F3L);
        for (int idx = tid; idx < 4096; idx += THREADS) {   // 8 ks, 8 nt
            int ln = idx & 31, rest = idx >> 5;
            int reg = rest & 1, ntk = rest >> 1;
            int nt = ntk & 7, ks = ntk >> 3;
            int n = nt * 8 + (ln >> 2);
            int k = ks * 16 + reg * 8 + (ln & 3) * 2;
            float w0 = W3[k * ODIM + n];
            float w1 = W3[(k + 1) * ODIM + n];
            uint16_t h0, l0, h1, l1;
            bsplit(w0, h0, l0); bsplit(w1, h1, l1);
            F3H[idx] = packu(h0, h1);
            F3L[idx] = packu(l0, l1);
        }
    }
    __syncthreads();

    const int p = tid & (TILE - 1);
    const int rh = tid >> 7;    // feature-half: 0 -> refs 0-5, 1 -> refs 6-9 + extras

    for (int tile = blockIdx.x; tile < ntiles; tile += gridDim.x) {
        const int pg0 = tile * TILE;

        // ---- feats -> act0 (packed hi/lo pairs, rows [p][words 0..7]) ----
        {
            int pg = pg0 + p;
            float th = coords[2 * pg];
            float phc = coords[2 * pg + 1];
            float ct = cosf(th), stt = sinf(th);
            uint2* dst = (uint2*)(smem + SM_ACT) + p * 68;
            if (rh == 0) {
                float fr[6];
                #pragma unroll
                for (int r = 0; r < 6; r++) {
                    float cd = ct * s_rc[r] + stt * s_rs[r] * cosf(phc - s_rp[r]);
                    cd = fminf(fmaxf(cd, -1.0f), 1.0f);
                    fr[r] = acosf(cd) * INV_PI;
                }
                dst[0] = pack_split(fr[0], fr[1]);
                dst[1] = pack_split(fr[2], fr[3]);
                dst[2] = pack_split(fr[4], fr[5]);
            } else {
                float fr[4];
                #pragma unroll
                for (int r = 0; r < 4; r++) {
                    float cd = ct * s_rc[r + 6] + stt * s_rs[r + 6] * cosf(phc - s_rp[r + 6]);
                    cd = fminf(fmaxf(cd, -1.0f), 1.0f);
                    fr[r] = acosf(cd) * INV_PI;
                }
                dst[3] = pack_split(fr[0], fr[1]);
                dst[4] = pack_split(fr[2], fr[3]);
                dst[5] = pack_split(th * INV_PI, phc * INV_2PI);
                dst[6] = pack_split(1.0f, 0.0f);
                dst[7] = make_uint2(0u, 0u);
            }
        }
        __syncthreads();

        // ---- L1: act0 @ W1  (K=16, N=128) + fused LN ----
        {
            float acc[2 * 8 * 4];
            #pragma unroll
            for (int i = 0; i < 64; i++) acc[i] = 0.0f;
            mma_layer<1, 8, 16>(smem, SM_F1H, SM_F1L, wm, wn, gid, tg, lane, acc);
            ln_frag_epilogue(smem, acc, wm, wn, gid, tg, s_b1, s_g1, s_bt1);
        }

        // ---- L2: act1 @ W2  (K=128, N=128) + fused LN ----
        {
            float acc[2 * 8 * 4];
            #pragma unroll
            for (int i = 0; i < 64; i++) acc[i] = 0.0f;
            mma_layer<8, 8, 16>(smem, SM_F2H, SM_F2L, wm, wn, gid, tg, lane, acc);
            ln_frag_epilogue(smem, acc, wm, wn, gid, tg, s_b2, s_g2, s_bt2);
        }

        // ---- L3: act2 @ W3  (K=128, N=64) -> GMEM directly ----
        {
            float acc[2 * 4 * 4];
            #pragma unroll
            for (int i = 0; i < 32; i++) acc[i] = 0.0f;
            mma_layer<8, 4, 8>(smem, SM_F3H, SM_F3L, wm, wn, gid, tg, lane, acc);
            #pragma unroll
            for (int mt = 0; mt < 2; mt++) {
                int r0 = wm * 32 + mt * 16 + gid;
                #pragma unroll
                for (int nt = 0; nt < 4; nt++) {
                    int col = (wn * 4 + nt) * 8 + tg * 2;
                    const float* a = acc + (size_t)(mt * 4 + nt) * 4;
                    float2 v0 = make_float2(a[0] + s_b3[col], a[1] + s_b3[col + 1]);
                    float2 v1 = make_float2(a[2] + s_b3[col], a[3] + s_b3[col + 1]);
                    *(float2*)(out + (size_t)(pg0 + r0) * ODIM + col)     = v0;
                    *(float2*)(out + (size_t)(pg0 + r0 + 8) * ODIM + col) = v1;
                }
            }
        }
        __syncthreads();   // act free for next tile's feats
    }
}

extern "C" void kernel_launch(void* const* d_in, const int* in_sizes, int n_in,
                              void* d_out, int out_size) {
    const float* coords    = (const float*)d_in[0];
    const float* ref_theta = (const float*)d_in[1];
    const float* ref_phi   = (const float*)d_in[2];
    const float* W1  = (const float*)d_in[3];
    const float* b1  = (const float*)d_in[4];
    const float* g1  = (const float*)d_in[5];
    const float* bt1 = (const float*)d_in[6];
    const float* W2  = (const float*)d_in[7];
    const float* b2  = (const float*)d_in[8];
    const float* g2  = (const float*)d_in[9];
    const float* bt2 = (const float*)d_in[10];
    const float* W3  = (const float*)d_in[11];
    const float* b3  = (const float*)d_in[12];
    float* out = (float*)d_out;

    int npoints = in_sizes[0] / 2;
    int ntiles = npoints / TILE;

    cudaFuncSetAttribute(trunk_kernel, cudaFuncAttributeMaxDynamicSharedMemorySize, SM_TOTAL);
    trunk_kernel<<<148, THREADS, SM_TOTAL>>>(
        coords, ref_theta, ref_phi,
        W1, b1, g1, bt1, W2, b2, g2, bt2, W3, b3,
        out, ntiles);
}

// round 8
// speedup vs baseline: 2.7549x; 1.0465x over previous
#include <cuda_runtime.h>
#include <cuda_bf16.h>
#include <cstdint>

#define THREADS 384
#define TILE    192
#define HDIM    128
#define FDIM    13
#define ODIM    64
#define NREF    10

#define INV_PI   0.31830988618379067f
#define INV_2PI  0.15915494309189535f

// ---------------- shared memory byte offsets ----------------
#define SM_RC     0
#define SM_RS     64
#define SM_RP     128
#define SM_B1     192
#define SM_G1     704
#define SM_BT1    1216
#define SM_B2     1728
#define SM_G2     2240
#define SM_BT2    2752
#define SM_B3     3264
#define SM_SRED   3520          /* 384 floats: [wn][row], rows=192 */
#define SM_S2RED  5056          /* 384 floats */
#define SM_ACT    6592          /* uint2[192][68] = 104448 B (hiPair, loPair) */
#define SM_F1H    (SM_ACT + 104448)   /* 111040 */
#define SM_F1L    (SM_F1H + 4096)
#define SM_F2H    (SM_F1L + 4096)
#define SM_F2L    (SM_F2H + 32768)
#define SM_F3H    (SM_F2L + 32768)
#define SM_F3L    (SM_F3H + 16384)
#define SM_TOTAL  (SM_F3L + 16384)    /* 217536 bytes */

// ---------------- helpers ----------------
__device__ __forceinline__ void bsplit(float v, uint16_t& h, uint16_t& l) {
    __nv_bfloat16 hb = __float2bfloat16_rn(v);
    float r = v - __bfloat162float(hb);
    __nv_bfloat16 lb = __float2bfloat16_rn(r);
    h = __bfloat16_as_ushort(hb);
    l = __bfloat16_as_ushort(lb);
}
__device__ __forceinline__ uint32_t packu(uint16_t lo, uint16_t hi) {
    return ((uint32_t)hi << 16) | (uint32_t)lo;
}
// fast split of a value pair: hi = truncate-to-bf16 (exact residual), lo = rn(residual)
__device__ __forceinline__ uint2 pack_split(float y0, float y1) {
    uint32_t b0 = __float_as_uint(y0), b1 = __float_as_uint(y1);
    float l0 = y0 - __uint_as_float(b0 & 0xFFFF0000u);
    float l1 = y1 - __uint_as_float(b1 & 0xFFFF0000u);
    uint32_t hp = __byte_perm(b0, b1, 0x7632);   // {hi16(b1), hi16(b0)}
    uint32_t lp;
    asm("cvt.rn.bf16x2.f32 %0, %1, %2;" : "=r"(lp) : "f"(l1), "f"(l0));
    return make_uint2(hp, lp);
}

// mma.sync m16n8k16 bf16: D += A*B  (fp32 accum)
__device__ __forceinline__ void mma16816(float* d, const uint32_t* a, uint32_t b0, uint32_t b1) {
    asm volatile(
        "mma.sync.aligned.m16n8k16.row.col.f32.bf16.bf16.f32 "
        "{%0,%1,%2,%3}, {%4,%5,%6,%7}, {%8,%9}, {%0,%1,%2,%3};"
        : "+f"(d[0]), "+f"(d[1]), "+f"(d[2]), "+f"(d[3])
        : "r"(a[0]), "r"(a[1]), "r"(a[2]), "r"(a[3]), "r"(b0), "r"(b1));
}

// One GEMM pass: acc[mt][nt][4] += act @ Wfrag ; warp owns 32 rows x (NTW*8) cols
template<int KS, int NTW, int NT_TOTAL>
__device__ __forceinline__ void mma_layer(char* smem, int fh_off, int fl_off,
                                          int wm, int wn, int gid, int tg, int lane,
                                          float* acc) {
    const uint2* A = (const uint2*)(smem + SM_ACT);
    const uint32_t* FH = (const uint32_t*)(smem + fh_off);
    const uint32_t* FL = (const uint32_t*)(smem + fl_off);
    #pragma unroll
    for (int ks = 0; ks < KS; ks++) {
        const int kc = ks * 8 + tg;
        uint32_t aH[2][4], aL[2][4];
        #pragma unroll
        for (int mt = 0; mt < 2; mt++) {
            int r0 = wm * 32 + mt * 16 + gid;
            uint2 v0 = A[r0 * 68 + kc];
            uint2 v1 = A[(r0 + 8) * 68 + kc];
            uint2 v2 = A[r0 * 68 + kc + 4];
            uint2 v3 = A[(r0 + 8) * 68 + kc + 4];
            aH[mt][0] = v0.x; aH[mt][1] = v1.x; aH[mt][2] = v2.x; aH[mt][3] = v3.x;
            aL[mt][0] = v0.y; aL[mt][1] = v1.y; aL[mt][2] = v2.y; aL[mt][3] = v3.y;
        }
        #pragma unroll
        for (int nt = 0; nt < NTW; nt++) {
            int ng = wn * NTW + nt;
            const uint32_t* fh = FH + (size_t)((ks * NT_TOTAL + ng) * 2) * 32 + lane;
            const uint32_t* fl = FL + (size_t)((ks * NT_TOTAL + ng) * 2) * 32 + lane;
            uint32_t bh0 = fh[0], bh1 = fh[32];
            uint32_t bl0 = fl[0], bl1 = fl[32];
            #pragma unroll
            for (int mt = 0; mt < 2; mt++) {
                float* a = acc + (size_t)(mt * NTW + nt) * 4;
                mma16816(a, aH[mt], bh0, bh1);
                mma16816(a, aL[mt], bh0, bh1);
                mma16816(a, aH[mt], bl0, bl1);
            }
        }
    }
}

// Fragment-resident LayerNorm + ReLU + split + act store (NTW=8 layers).
// acc rows: r(mt,h) = wm*32 + mt*16 + h*8 + gid ; cols: c = (wn*8+nt)*8 + 2tg + {0,1}
__device__ __forceinline__ void ln_frag_epilogue(char* smem, float* acc,
                                                 int wm, int wn, int gid, int tg,
                                                 const float* bias, const float* g,
                                                 const float* bt) {
    float* SS = (float*)(smem + SM_SRED);
    float* QQ = (float*)(smem + SM_S2RED);
    float s[2][2], q[2][2];
    #pragma unroll
    for (int mt = 0; mt < 2; mt++) { s[mt][0]=s[mt][1]=q[mt][0]=q[mt][1]=0.0f; }
    #pragma unroll
    for (int mt = 0; mt < 2; mt++) {
        #pragma unroll
        for (int nt = 0; nt < 8; nt++) {
            float* a = acc + (size_t)(mt * 8 + nt) * 4;
            int c0 = (wn * 8 + nt) * 8 + 2 * tg;
            float b0v = bias[c0], b1v = bias[c0 + 1];
            a[0] += b0v; a[1] += b1v; a[2] += b0v; a[3] += b1v;
            s[mt][0] += a[0] + a[1];
            q[mt][0] = fmaf(a[0], a[0], q[mt][0]);
            q[mt][0] = fmaf(a[1], a[1], q[mt][0]);
            s[mt][1] += a[2] + a[3];
            q[mt][1] = fmaf(a[2], a[2], q[mt][1]);
            q[mt][1] = fmaf(a[3], a[3], q[mt][1]);
        }
    }
    // reduce over the 4 tg lanes (lanes gid*4 + tg)
    #pragma unroll
    for (int mt = 0; mt < 2; mt++) {
        #pragma unroll
        for (int h = 0; h < 2; h++) {
            s[mt][h] += __shfl_xor_sync(0xffffffffu, s[mt][h], 1);
            s[mt][h] += __shfl_xor_sync(0xffffffffu, s[mt][h], 2);
            q[mt][h] += __shfl_xor_sync(0xffffffffu, q[mt][h], 1);
            q[mt][h] += __shfl_xor_sync(0xffffffffu, q[mt][h], 2);
        }
    }
    if (tg == 0) {
        #pragma unroll
        for (int mt = 0; mt < 2; mt++) {
            #pragma unroll
            for (int h = 0; h < 2; h++) {
                int row = wm * 32 + mt * 16 + h * 8 + gid;
                SS[wn * TILE + row] = s[mt][h];
                QQ[wn * TILE + row] = q[mt][h];
            }
        }
    }
    __syncthreads();   // also guarantees all MMA act-reads complete
    float mu[2][2], rs[2][2];
    #pragma unroll
    for (int mt = 0; mt < 2; mt++) {
        #pragma unroll
        for (int h = 0; h < 2; h++) {
            int row = wm * 32 + mt * 16 + h * 8 + gid;
            float st = SS[row] + SS[TILE + row];
            float sq = QQ[row] + QQ[TILE + row];
            float m = st * (1.0f / HDIM);
            float var = sq * (1.0f / HDIM) - m * m;
            mu[mt][h] = m;
            rs[mt][h] = rsqrtf(var + 1e-5f);
        }
    }
    uint2* ACT = (uint2*)(smem + SM_ACT);
    #pragma unroll
    for (int mt = 0; mt < 2; mt++) {
        int r0 = wm * 32 + mt * 16 + gid;
        #pragma unroll
        for (int nt = 0; nt < 8; nt++) {
            float* a = acc + (size_t)(mt * 8 + nt) * 4;
            int c0 = (wn * 8 + nt) * 8 + 2 * tg;
            float g0 = g[c0], g1 = g[c0 + 1], t0 = bt[c0], t1 = bt[c0 + 1];
            float y00 = fmaxf(fmaf((a[0] - mu[mt][0]) * rs[mt][0], g0, t0), 0.0f);
            float y01 = fmaxf(fmaf((a[1] - mu[mt][0]) * rs[mt][0], g1, t1), 0.0f);
            float y10 = fmaxf(fmaf((a[2] - mu[mt][1]) * rs[mt][1], g0, t0), 0.0f);
            float y11 = fmaxf(fmaf((a[3] - mu[mt][1]) * rs[mt][1], g1, t1), 0.0f);
            int w = (wn * 8 + nt) * 4 + tg;
            ACT[r0 * 68 + w]       = pack_split(y00, y01);
            ACT[(r0 + 8) * 68 + w] = pack_split(y10, y11);
        }
    }
    __syncthreads();
}

__global__ __launch_bounds__(THREADS, 1)
void trunk_kernel(const float* __restrict__ coords,
                  const float* __restrict__ ref_theta, const float* __restrict__ ref_phi,
                  const float* __restrict__ W1, const float* __restrict__ b1,
                  const float* __restrict__ g1, const float* __restrict__ bt1,
                  const float* __restrict__ W2, const float* __restrict__ b2,
                  const float* __restrict__ g2, const float* __restrict__ bt2,
                  const float* __restrict__ W3, const float* __restrict__ b3,
                  float* __restrict__ out, int ntiles, int npoints) {
    extern __shared__ char smem[];
    const int tid = threadIdx.x;
    const int lane = tid & 31;
    const int wid = tid >> 5;
    const int gid = lane >> 2;
    const int tg = lane & 3;
    const int wm = wid % 6;       // 6 m-positions x 32 rows = 192
    const int wn = wid / 6;       // 2 n-halves

    float* s_b1 = (float*)(smem + SM_B1);
    float* s_g1 = (float*)(smem + SM_G1);
    float* s_bt1 = (float*)(smem + SM_BT1);
    float* s_b2 = (float*)(smem + SM_B2);
    float* s_g2 = (float*)(smem + SM_G2);
    float* s_bt2 = (float*)(smem + SM_BT2);
    float* s_b3 = (float*)(smem + SM_B3);
    float* s_rc = (float*)(smem + SM_RC);
    float* s_rs = (float*)(smem + SM_RS);
    float* s_rp = (float*)(smem + SM_RP);

    // ---- one-time staging: biases / LN params / refs ----
    for (int i = tid; i < HDIM; i += THREADS) {
        s_b1[i] = b1[i]; s_g1[i] = g1[i]; s_bt1[i] = bt1[i];
        s_b2[i] = b2[i]; s_g2[i] = g2[i]; s_bt2[i] = bt2[i];
    }
    for (int i = tid; i < ODIM; i += THREADS) s_b3[i] = b3[i];
    if (tid < NREF) {
        float t = ref_theta[tid];
        s_rc[tid] = cosf(t); s_rs[tid] = sinf(t); s_rp[tid] = ref_phi[tid];
    }

    // ---- one-time fragment-ordered weight conversion ----
    // layout: word index = ((ks*NT + ntile)*2 + reg)*32 + lane
    {
        uint32_t* F1H = (uint32_t*)(smem + SM_F1H);
        uint32_t* F1L = (uint32_t*)(smem + SM_F1L);
        for (int idx = tid; idx < 1024; idx += THREADS) {   // 1 ks, 16 nt
            int ln = idx & 31, rest = idx >> 5;
            int reg = rest & 1, nt = rest >> 1;
            int n = nt * 8 + (ln >> 2);
            int k = reg * 8 + (ln & 3) * 2;
            float w0 = (k < FDIM)     ? W1[k * HDIM + n]       : 0.0f;
            float w1 = (k + 1 < FDIM) ? W1[(k + 1) * HDIM + n] : 0.0f;
            uint16_t h0, l0, h1, l1;
            bsplit(w0, h0, l0); bsplit(w1, h1, l1);
            F1H[idx] = packu(h0, h1);
            F1L[idx] = packu(l0, l1);
        }
        uint32_t* F2H = (uint32_t*)(smem + SM_F2H);
        uint32_t* F2L = (uint32_t*)(smem + SM_F2L);
        for (int idx = tid; idx < 8192; idx += THREADS) {   // 8 ks, 16 nt
            int ln = idx & 31, rest = idx >> 5;
            int reg = rest & 1, ntk = rest >> 1;
            int nt = ntk & 15, ks = ntk >> 4;
            int n = nt * 8 + (ln >> 2);
            int k = ks * 16 + reg * 8 + (ln & 3) * 2;
            float w0 = W2[k * HDIM + n];
            float w1 = W2[(k + 1) * HDIM + n];
            uint16_t h0, l0, h1, l1;
            bsplit(w0, h0, l0); bsplit(w1, h1, l1);
            F2H[idx] = packu(h0, h1);
            F2L[idx] = packu(l0, l1);
        }
        uint32_t* F3H = (uint32_t*)(smem + SM_F3H);
        uint32_t* F3L = (uint32_t*)(smem + SM_F3L);
        for (int idx = tid; idx < 4096; idx += THREADS) {   // 8 ks, 8 nt
            int ln = idx & 31, rest = idx >> 5;
            int reg = rest & 1, ntk = rest >> 1;
            int nt = ntk & 7, ks = ntk >> 3;
            int n = nt * 8 + (ln >> 2);
            int k = ks * 16 + reg * 8 + (ln & 3) * 2;
            float w0 = W3[k * ODIM + n];
            float w1 = W3[(k + 1) * ODIM + n];
            uint16_t h0, l0, h1, l1;
            bsplit(w0, h0, l0); bsplit(w1, h1, l1);
            F3H[idx] = packu(h0, h1);
            F3L[idx] = packu(l0, l1);
        }
    }
    __syncthreads();

    const int p = (tid < TILE) ? tid : (tid - TILE);   // point row 0..191
    const int rh = (tid < TILE) ? 0 : 1;               // feature-half

    for (int tile = blockIdx.x; tile < ntiles; tile += gridDim.x) {
        const int pg0 = tile * TILE;

        // ---- feats -> act0 (packed hi/lo pairs, rows [p][words 0..7]) ----
        {
            int pg = pg0 + p;
            if (pg >= npoints) pg = npoints - 1;        // clamp (garbage rows are row-local)
            float th = coords[2 * pg];
            float phc = coords[2 * pg + 1];
            float ct = cosf(th), stt = sinf(th);
            uint2* dst = (uint2*)(smem + SM_ACT) + p * 68;
            if (rh == 0) {
                float fr[6];
                #pragma unroll
                for (int r = 0; r < 6; r++) {
                    float cd = ct * s_rc[r] + stt * s_rs[r] * cosf(phc - s_rp[r]);
                    cd = fminf(fmaxf(cd, -1.0f), 1.0f);
                    fr[r] = acosf(cd) * INV_PI;
                }
                dst[0] = pack_split(fr[0], fr[1]);
                dst[1] = pack_split(fr[2], fr[3]);
                dst[2] = pack_split(fr[4], fr[5]);
            } else {
                float fr[4];
                #pragma unroll
                for (int r = 0; r < 4; r++) {
                    float cd = ct * s_rc[r + 6] + stt * s_rs[r + 6] * cosf(phc - s_rp[r + 6]);
                    cd = fminf(fmaxf(cd, -1.0f), 1.0f);
                    fr[r] = acosf(cd) * INV_PI;
                }
                dst[3] = pack_split(fr[0], fr[1]);
                dst[4] = pack_split(fr[2], fr[3]);
                dst[5] = pack_split(th * INV_PI, phc * INV_2PI);
                dst[6] = pack_split(1.0f, 0.0f);
                dst[7] = make_uint2(0u, 0u);
            }
        }
        __syncthreads();

        // ---- L1: act0 @ W1  (K=16, N=128) + fused LN ----
        {
            float acc[2 * 8 * 4];
            #pragma unroll
            for (int i = 0; i < 64; i++) acc[i] = 0.0f;
            mma_layer<1, 8, 16>(smem, SM_F1H, SM_F1L, wm, wn, gid, tg, lane, acc);
            ln_frag_epilogue(smem, acc, wm, wn, gid, tg, s_b1, s_g1, s_bt1);
        }

        // ---- L2: act1 @ W2  (K=128, N=128) + fused LN ----
        {
            float acc[2 * 8 * 4];
            #pragma unroll
            for (int i = 0; i < 64; i++) acc[i] = 0.0f;
            mma_layer<8, 8, 16>(smem, SM_F2H, SM_F2L, wm, wn, gid, tg, lane, acc);
            ln_frag_epilogue(smem, acc, wm, wn, gid, tg, s_b2, s_g2, s_bt2);
        }

        // ---- L3: act2 @ W3  (K=128, N=64) -> GMEM directly ----
        {
            float acc[2 * 4 * 4];
            #pragma unroll
            for (int i = 0; i < 32; i++) acc[i] = 0.0f;
            mma_layer<8, 4, 8>(smem, SM_F3H, SM_F3L, wm, wn, gid, tg, lane, acc);
            #pragma unroll
            for (int mt = 0; mt < 2; mt++) {
                int r0 = wm * 32 + mt * 16 + gid;
                #pragma unroll
                for (int nt = 0; nt < 4; nt++) {
                    int col = (wn * 4 + nt) * 8 + tg * 2;
                    const float* a = acc + (size_t)(mt * 4 + nt) * 4;
                    if (pg0 + r0 < npoints) {
                        *(float2*)(out + (size_t)(pg0 + r0) * ODIM + col) =
                            make_float2(a[0] + s_b3[col], a[1] + s_b3[col + 1]);
                    }
                    if (pg0 + r0 + 8 < npoints) {
                        *(float2*)(out + (size_t)(pg0 + r0 + 8) * ODIM + col) =
                            make_float2(a[2] + s_b3[col], a[3] + s_b3[col + 1]);
                    }
                }
            }
        }
        __syncthreads();   // act free for next tile's feats
    }
}

extern "C" void kernel_launch(void* const* d_in, const int* in_sizes, int n_in,
                              void* d_out, int out_size) {
    const float* coords    = (const float*)d_in[0];
    const float* ref_theta = (const float*)d_in[1];
    const float* ref_phi   = (const float*)d_in[2];
    const float* W1  = (const float*)d_in[3];
    const float* b1  = (const float*)d_in[4];
    const float* g1  = (const float*)d_in[5];
    const float* bt1 = (const float*)d_in[6];
    const float* W2  = (const float*)d_in[7];
    const float* b2  = (const float*)d_in[8];
    const float* g2  = (const float*)d_in[9];
    const float* bt2 = (const float*)d_in[10];
    const float* W3  = (const float*)d_in[11];
    const float* b3  = (const float*)d_in[12];
    float* out = (float*)d_out;

    int npoints = in_sizes[0] / 2;
    int ntiles = (npoints + TILE - 1) / TILE;

    cudaFuncSetAttribute(trunk_kernel, cudaFuncAttributeMaxDynamicSharedMemorySize, SM_TOTAL);
    trunk_kernel<<<148, THREADS, SM_TOTAL>>>(
        coords, ref_theta, ref_phi,
        W1, b1, g1, bt1, W2, b2, g2, bt2, W3, b3,
        out, ntiles, npoints);
}